// round 13
// baseline (speedup 1.0000x reference)
#include <cuda_runtime.h>
#include <cstdint>

// Problem dims
#define DM 8192
#define DK 2048
#define DN 2048

// GEMM tiling: CTA 128x128, 8 warps in 4(M) x 2(N), warp tile 32x64. 2 CTAs/SM.
constexpr int TM = 128;
constexpr int TN = 128;
constexpr int TKC = 128;           // K bytes per stage (4 ks sub-chunks)
constexpr int ST = 3;              // pipeline stages
constexpr int NK = DK / TKC;       // 16 chunks per tile
constexpr int NTILES = (DM / TM) * (DN / TN);   // 1024
constexpr int NBLKN = DN / TN;     // 16
constexpr int PERSIST_CTAS = 296;  // 2 per SM

// Tile-contiguous, pre-swizzled operand layout (16KB tiles):
//   g_A2[mblk][kc][row 0..127][col ^ ((row&7)<<4)]
constexpr int TILE_BYTES = 128 * 128;          // 16384
constexpr int A_ST = TILE_BYTES;
constexpr int STAGE = 2 * TILE_BYTES;          // 32768

// smem header: full[ST] @0, empty[ST] @32, tile-broadcast @64, data @128
constexpr uint32_t OFF_FULL = 0;
constexpr uint32_t OFF_EMPTY = 32;
constexpr int SMEM_DATA = 128;
constexpr int SMEM_BYTES = SMEM_DATA + ST * STAGE;   // 98432 -> 2 CTAs/SM

// s8 scratch (allocation-free __device__ globals)
__device__ int8_t g_A2[(size_t)DM * DK];
__device__ int8_t g_B2[(size_t)DN * DK];
__device__ int g_tile_counter;

// ---------------- helpers ----------------
__device__ __forceinline__ uint32_t smem_u32(const void* p) {
    uint32_t a;
    asm("{ .reg .u64 t; cvta.to.shared.u64 t, %1; cvt.u32.u64 %0, t; }" : "=r"(a) : "l"(p));
    return a;
}

__device__ __forceinline__ void ldm_x4(uint32_t* r, uint32_t addr) {
    asm volatile("ldmatrix.sync.aligned.m8n8.x4.shared.b16 {%0,%1,%2,%3}, [%4];"
                 : "=r"(r[0]), "=r"(r[1]), "=r"(r[2]), "=r"(r[3]) : "r"(addr));
}

// mbarrier primitives
#define MBARRIER_INIT(addr, count) \
    asm volatile("mbarrier.init.shared.b64 [%0], %1;" :: "r"((uint32_t)(addr)), "r"((uint32_t)(count)) : "memory")
#define MBARRIER_ARRIVE(addr) \
    asm volatile("mbarrier.arrive.shared.b64 _, [%0];" :: "r"((uint32_t)(addr)) : "memory")
#define MBARRIER_EXPECT_TX(addr, bytes) \
    asm volatile("mbarrier.arrive.expect_tx.shared.b64 _, [%0], %1;" :: "r"((uint32_t)(addr)), "r"((uint32_t)(bytes)) : "memory")

// 1D bulk copy gmem->smem with transaction-count completion (sm_90 baseline)
#define CP_BULK_G2S(dst_u32, src_ptr, bytes, mbar_u32) \
    asm volatile("cp.async.bulk.shared::cluster.global.mbarrier::complete_tx::bytes [%0], [%1], %2, [%3];" \
                 :: "r"((uint32_t)(dst_u32)), "l"(src_ptr), "r"((uint32_t)(bytes)), "r"((uint32_t)(mbar_u32)) : "memory")

#define MBARRIER_WAIT_PARITY(mbar_smem_addr, phase_parity) do { \
    uint32_t _mbar = (uint32_t)(mbar_smem_addr); \
    uint32_t _parity = (uint32_t)(phase_parity); \
    uint32_t _done; \
    asm volatile( \
        "{\n\t.reg .pred p;\n\t" \
        "mbarrier.try_wait.parity.acquire.cta.shared::cta.b64 p, [%1], %2;\n\t" \
        "selp.b32 %0, 1, 0, p;\n\t}" \
        : "=r"(_done) : "r"(_mbar), "r"(_parity) : "memory"); \
    if (!_done) { \
        asm volatile( \
            "{\n\t.reg .pred P1;\n\t" \
            "WAIT_LOOP_%=:\n\t" \
            "mbarrier.try_wait.parity.acquire.cta.shared::cta.b64 P1, [%0], %1, 0x989680;\n\t" \
            "@P1 bra.uni WAIT_DONE_%=;\n\t" \
            "bra.uni WAIT_LOOP_%=;\n\t" \
            "WAIT_DONE_%=:\n\t}" \
            :: "r"(_mbar), "r"(_parity) : "memory"); \
    } \
} while (0)

// s8 MMA: D(16x8,s32) += A(16x32,s8 row) * B(32x8,s8 col)
#define MMA_S8(C, A, B0, B1) \
    asm volatile("mma.sync.aligned.m16n8k32.row.col.s32.s8.s8.s32 " \
        "{%0,%1,%2,%3}, {%4,%5,%6,%7}, {%8,%9}, {%0,%1,%2,%3};" \
        : "+r"((C)[0]), "+r"((C)[1]), "+r"((C)[2]), "+r"((C)[3]) \
        : "r"((A)[0]), "r"((A)[1]), "r"((A)[2]), "r"((A)[3]), \
          "r"(B0), "r"(B1))

__device__ __forceinline__ float isgn(int v) {
    return (v > 0) ? 1.0f : ((v < 0) ? -1.0f : 0.0f);
}

// ---------------- tile counter reset (graph-replay determinism) ----------------
__global__ void reset_counter_kernel() { g_tile_counter = 0; }

// ---------------- conversion: fp32 (+-1) -> pre-swizzled tile-contiguous s8 ----------------
constexpr int NA4 = DM * DK / 4;
constexpr int NW4 = DN * DK / 4;
__global__ void cvt_kernel(const float4* __restrict__ a, const float4* __restrict__ w) {
    int i = blockIdx.x * blockDim.x + threadIdx.x;
    const float4* src;
    uint32_t* dst;
    int o;
    if (i < NA4) {
        src = a; dst = reinterpret_cast<uint32_t*>(g_A2); o = i;
    } else {
        o = i - NA4;
        if (o >= NW4) return;
        src = w; dst = reinterpret_cast<uint32_t*>(g_B2);
    }
    int tile = o >> 12;
    int wi = o & 4095;
    int row = wi >> 5;
    int wcol = wi & 31;
    int col_byte = (wcol * 4) ^ ((row & 7) << 4);
    int blk = tile >> 4;
    int kc = tile & 15;
    int f4 = (((blk * 128 + row) * 2048) + kc * 128 + col_byte) >> 2;
    float4 v = src[f4];
    uint32_t p = (uint32_t)(uint8_t)(int8_t)(v.x > 0.0f ? 1 : -1)
               | ((uint32_t)(uint8_t)(int8_t)(v.y > 0.0f ? 1 : -1) << 8)
               | ((uint32_t)(uint8_t)(int8_t)(v.z > 0.0f ? 1 : -1) << 16)
               | ((uint32_t)(uint8_t)(int8_t)(v.w > 0.0f ? 1 : -1) << 24);
    dst[o] = p;
}

// ---------------- persistent GEMM + sign kernel ----------------
__global__ void __launch_bounds__(256, 2) binlinear_gemm_kernel(float* __restrict__ out) {
    extern __shared__ int8_t smem[];
    const uint32_t sb = smem_u32(smem);
    __shared__ int s_tile;
    const int tid = threadIdx.x;
    const int wid = tid >> 5;
    const int lane = tid & 31;
    const int g = lane >> 2;      // 0..7
    const int tig = lane & 3;     // 0..3
    const int wm = (wid & 3) * 32;     // warp M offset
    const int wn = (wid >> 2) * 64;    // warp N offset

    if (tid == 0) {
        #pragma unroll
        for (int s = 0; s < ST; ++s) {
            MBARRIER_INIT(sb + OFF_FULL + s * 8, 1);    // expect_tx arrive + 32KB tx
            MBARRIER_INIT(sb + OFF_EMPTY + s * 8, 8);   // one arrive per warp
        }
    }
    __syncthreads();

    // per-lane ldmatrix bases in the swizzled 128B-row layout
    const int rowA0 = wm + (lane & 15);
    const uint32_t aRow0 = (uint32_t)rowA0 * 128;
    const uint32_t aRow1 = aRow0 + 16 * 128;
    const uint32_t swzA = (uint32_t)(rowA0 & 7) << 4;
    const uint32_t asegb = (uint32_t)(lane >> 4) << 4;

    const int rowB = wn + (lane >> 4) * 8 + (lane & 7);
    const uint32_t bRow = (uint32_t)rowB * 128;
    const uint32_t swzB = (uint32_t)(rowB & 7) << 4;
    const uint32_t bsegb = (uint32_t)(lane & 8) << 1;

    // ring cursors persist across tiles
    int pst = 0, pph = 1;
    int cst = 0, cph = 0;

    while (true) {
        if (tid == 0) s_tile = atomicAdd(&g_tile_counter, 1);
        __syncthreads();
        const int t = s_tile;
        if (t >= NTILES) break;
        const int mblk = t >> 4;          // NBLKN == 16
        const int nblk = t & (NBLKN - 1);

        int c[2][8][4];
        #pragma unroll
        for (int mt = 0; mt < 2; ++mt)
            #pragma unroll
            for (int nt = 0; nt < 8; ++nt)
                #pragma unroll
                for (int r = 0; r < 4; ++r) c[mt][nt][r] = 0;

        const int8_t* gA = g_A2 + (size_t)(mblk * 16) * TILE_BYTES;
        const int8_t* gB = g_B2 + (size_t)(nblk * 16) * TILE_BYTES;

        // prologue: produce chunks 0..ST-2 of this tile
        if (tid == 0) {
            #pragma unroll
            for (int s = 0; s < ST - 1; ++s) {
                MBARRIER_WAIT_PARITY(sb + OFF_EMPTY + pst * 8, pph);
                const uint32_t full = sb + OFF_FULL + pst * 8;
                MBARRIER_EXPECT_TX(full, STAGE);
                const uint32_t Ab = sb + SMEM_DATA + pst * STAGE;
                CP_BULK_G2S(Ab, gA + (size_t)s * TILE_BYTES, TILE_BYTES, full);
                CP_BULK_G2S(Ab + A_ST, gB + (size_t)s * TILE_BYTES, TILE_BYTES, full);
                if (++pst == ST) { pst = 0; pph ^= 1; }
            }
        } else {
            // keep non-producer threads' cursor view consistent
            #pragma unroll
            for (int s = 0; s < ST - 1; ++s)
                if (++pst == ST) { pst = 0; pph ^= 1; }
        }

        for (int i = 0; i < NK; ++i) {
            if (i + ST - 1 < NK) {
                if (tid == 0) {
                    MBARRIER_WAIT_PARITY(sb + OFF_EMPTY + pst * 8, pph);
                    const uint32_t full = sb + OFF_FULL + pst * 8;
                    MBARRIER_EXPECT_TX(full, STAGE);
                    const uint32_t Ab = sb + SMEM_DATA + pst * STAGE;
                    const size_t kc = (size_t)(i + ST - 1) * TILE_BYTES;
                    CP_BULK_G2S(Ab, gA + kc, TILE_BYTES, full);
                    CP_BULK_G2S(Ab + A_ST, gB + kc, TILE_BYTES, full);
                }
                if (++pst == ST) { pst = 0; pph ^= 1; }
            }

            // consume stage cst
            MBARRIER_WAIT_PARITY(sb + OFF_FULL + cst * 8, cph);
            const uint32_t Ab = sb + SMEM_DATA + cst * STAGE;
            const uint32_t Bb = Ab + A_ST;
            #pragma unroll
            for (int ks = 0; ks < 4; ++ks) {
                const uint32_t k0 = (uint32_t)ks * 32;
                uint32_t a[2][4];
                ldm_x4(a[0], Ab + aRow0 + ((asegb + k0) ^ swzA));
                ldm_x4(a[1], Ab + aRow1 + ((asegb + k0) ^ swzA));
                #pragma unroll
                for (int p = 0; p < 4; ++p) {
                    uint32_t bt[4];
                    ldm_x4(bt, Bb + bRow + (uint32_t)p * 2048 + ((bsegb + k0) ^ swzB));
                    MMA_S8(c[0][2 * p + 0], a[0], bt[0], bt[1]);
                    MMA_S8(c[0][2 * p + 1], a[0], bt[2], bt[3]);
                    MMA_S8(c[1][2 * p + 0], a[1], bt[0], bt[1]);
                    MMA_S8(c[1][2 * p + 1], a[1], bt[2], bt[3]);
                }
            }
            __syncwarp();
            if (lane == 0) MBARRIER_ARRIVE(sb + OFF_EMPTY + cst * 8);
            if (++cst == ST) { cst = 0; cph ^= 1; }
        }

        // ---- epilogue for tile t: sign -> float, 8B vectorized stores ----
        const int m0 = mblk * TM;
        const int n0 = nblk * TN;
        #pragma unroll
        for (int mt = 0; mt < 2; ++mt) {
            const int row0 = m0 + wm + mt * 16 + g;
            float* o0 = out + (size_t)row0 * DN + n0 + wn;
            float* o1 = out + (size_t)(row0 + 8) * DN + n0 + wn;
            #pragma unroll
            for (int nt = 0; nt < 8; ++nt) {
                const int col = nt * 8 + tig * 2;
                float2 v0 = make_float2(isgn(c[mt][nt][0]), isgn(c[mt][nt][1]));
                float2 v1 = make_float2(isgn(c[mt][nt][2]), isgn(c[mt][nt][3]));
                *reinterpret_cast<float2*>(o0 + col) = v0;
                *reinterpret_cast<float2*>(o1 + col) = v1;
            }
        }
        // s_tile may be rewritten only after the next __syncthreads at loop top
    }
}

// ---------------- launch ----------------
extern "C" void kernel_launch(void* const* d_in, const int* in_sizes, int n_in,
                              void* d_out, int out_size) {
    const float* a = (const float*)d_in[0];
    const float* w = (const float*)d_in[1];
    if (n_in >= 2 && in_sizes[0] < in_sizes[1]) {
        const float* t = a; a = w; w = t;
    }

    reset_counter_kernel<<<1, 1>>>();
    {
        int total = NA4 + NW4;
        cvt_kernel<<<(total + 255) / 256, 256>>>((const float4*)a, (const float4*)w);
    }

    static bool attr_set = false;
    if (!attr_set) {
        cudaFuncSetAttribute(binlinear_gemm_kernel,
                             cudaFuncAttributeMaxDynamicSharedMemorySize, SMEM_BYTES);
        attr_set = true;
    }
    binlinear_gemm_kernel<<<PERSIST_CTAS, 256, SMEM_BYTES>>>((float*)d_out);
}

// round 17
// speedup vs baseline: 1.1021x; 1.1021x over previous
#include <cuda_runtime.h>
#include <cstdint>

// Problem dims
#define DM 8192
#define DK 2048
#define DN 2048

// GEMM tiling: CTA 128x128, 8 warps in 4(M) x 2(N), warp tile 32x64. 2 CTAs/SM.
constexpr int TM = 128;
constexpr int TN = 128;
constexpr int TKC = 128;           // K bytes per stage (4 ks sub-chunks)
constexpr int ST = 3;              // pipeline stages
constexpr int NK = DK / TKC;       // 16 chunks

// Tile-contiguous, pre-swizzled operand layout (16KB tiles):
//   g_A2[mblk][kc][row 0..127][col ^ ((row&7)<<4)]
constexpr int TILE_BYTES = 128 * 128;          // 16384
constexpr int A_ST = TILE_BYTES;
constexpr int STAGE = 2 * TILE_BYTES;          // 32768

// smem header: full[ST] @0, empty[ST] @32, data @128
constexpr uint32_t OFF_FULL = 0;
constexpr uint32_t OFF_EMPTY = 32;
constexpr uint32_t SMEM_DATA = 128;
constexpr int SMEM_BYTES = SMEM_DATA + ST * STAGE;   // 98432 -> 2 CTAs/SM

// s8 scratch (allocation-free __device__ globals)
__device__ int8_t g_A2[(size_t)DM * DK];
__device__ int8_t g_B2[(size_t)DN * DK];

// ---------------- helpers ----------------
__device__ __forceinline__ uint32_t smem_u32(const void* p) {
    uint32_t a;
    asm("{ .reg .u64 t; cvta.to.shared.u64 t, %1; cvt.u32.u64 %0, t; }" : "=r"(a) : "l"(p));
    return a;
}

__device__ __forceinline__ void ldm_x4(uint32_t* r, uint32_t addr) {
    asm volatile("ldmatrix.sync.aligned.m8n8.x4.shared.b16 {%0,%1,%2,%3}, [%4];"
                 : "=r"(r[0]), "=r"(r[1]), "=r"(r[2]), "=r"(r[3]) : "r"(addr));
}

// mbarrier primitives
#define MBARRIER_INIT(addr, count) \
    asm volatile("mbarrier.init.shared.b64 [%0], %1;" :: "r"((uint32_t)(addr)), "r"((uint32_t)(count)) : "memory")
#define MBARRIER_ARRIVE(addr) \
    asm volatile("mbarrier.arrive.shared.b64 _, [%0];" :: "r"((uint32_t)(addr)) : "memory")
#define MBARRIER_EXPECT_TX(addr, bytes) \
    asm volatile("mbarrier.arrive.expect_tx.shared.b64 _, [%0], %1;" :: "r"((uint32_t)(addr)), "r"((uint32_t)(bytes)) : "memory")

// 1D bulk copy gmem->smem with transaction-count completion (sm_90 baseline)
#define CP_BULK_G2S(dst_u32, src_ptr, bytes, mbar_u32) \
    asm volatile("cp.async.bulk.shared::cluster.global.mbarrier::complete_tx::bytes [%0], [%1], %2, [%3];" \
                 :: "r"((uint32_t)(dst_u32)), "l"(src_ptr), "r"((uint32_t)(bytes)), "r"((uint32_t)(mbar_u32)) : "memory")

#define MBARRIER_WAIT_PARITY(mbar_smem_addr, phase_parity) do { \
    uint32_t _mbar = (uint32_t)(mbar_smem_addr); \
    uint32_t _parity = (uint32_t)(phase_parity); \
    uint32_t _done; \
    asm volatile( \
        "{\n\t.reg .pred p;\n\t" \
        "mbarrier.try_wait.parity.acquire.cta.shared::cta.b64 p, [%1], %2;\n\t" \
        "selp.b32 %0, 1, 0, p;\n\t}" \
        : "=r"(_done) : "r"(_mbar), "r"(_parity) : "memory"); \
    if (!_done) { \
        asm volatile( \
            "{\n\t.reg .pred P1;\n\t" \
            "WAIT_LOOP_%=:\n\t" \
            "mbarrier.try_wait.parity.acquire.cta.shared::cta.b64 P1, [%0], %1, 0x989680;\n\t" \
            "@P1 bra.uni WAIT_DONE_%=;\n\t" \
            "bra.uni WAIT_LOOP_%=;\n\t" \
            "WAIT_DONE_%=:\n\t}" \
            :: "r"(_mbar), "r"(_parity) : "memory"); \
    } \
} while (0)

// s8 MMA: D(16x8,s32) += A(16x32,s8 row) * B(32x8,s8 col)
#define MMA_S8(C, A, B0, B1) \
    asm volatile("mma.sync.aligned.m16n8k32.row.col.s32.s8.s8.s32 " \
        "{%0,%1,%2,%3}, {%4,%5,%6,%7}, {%8,%9}, {%0,%1,%2,%3};" \
        : "+r"((C)[0]), "+r"((C)[1]), "+r"((C)[2]), "+r"((C)[3]) \
        : "r"((A)[0]), "r"((A)[1]), "r"((A)[2]), "r"((A)[3]), \
          "r"(B0), "r"(B1))

__device__ __forceinline__ float isgn(int v) {
    return (v > 0) ? 1.0f : ((v < 0) ? -1.0f : 0.0f);
}

// ---------------- conversion v2: fp32 (+-1) -> pre-swizzled tile-contiguous s8 ----------
// Each thread emits 16 consecutive output bytes (uint4) from 16 consecutive input floats.
// sign byte select, carry-free SWAR: s in {0,1} per byte lane ->
//   p = 0x01010101 ^ (s * 0xFE)
constexpr int NA4 = DM * DK / 4;
constexpr int NW4 = DN * DK / 4;
constexpr int NA16 = NA4 / 4;
constexpr int NW16 = NW4 / 4;
__device__ __forceinline__ uint32_t sgnword(uint4 u) {
    uint32_t s = (u.x >> 31) | ((u.y >> 31) << 8) | ((u.z >> 31) << 16) | ((u.w >> 31) << 24);
    return 0x01010101u ^ (s * 0xFEu);
}
__global__ void cvt_kernel(const uint4* __restrict__ a, const uint4* __restrict__ w) {
    int i = blockIdx.x * blockDim.x + threadIdx.x;
    const uint4* src;
    uint4* dst;
    int o16;
    if (i < NA16) {
        src = a; dst = reinterpret_cast<uint4*>(g_A2); o16 = i;
    } else {
        o16 = i - NA16;
        if (o16 >= NW16) return;
        src = w; dst = reinterpret_cast<uint4*>(g_B2);
    }
    int o0 = o16 * 4;               // first output word
    int tile = o0 >> 12;
    int wi = o0 & 4095;
    int row = wi >> 5;
    int wcol0 = wi & 31;            // multiple of 4
    int col_byte = (wcol0 * 4) ^ ((row & 7) << 4);   // multiple of 16
    int blk = tile >> 4;
    int kc = tile & 15;
    // float index of the first of 16 consecutive source floats; uint4 index = /4
    int fidx = ((blk * 128 + row) * 2048) + kc * 128 + col_byte;
    int f16 = fidx >> 2;            // uint4 = 4 floats
    uint4 v0 = src[f16 + 0];
    uint4 v1 = src[f16 + 1];
    uint4 v2 = src[f16 + 2];
    uint4 v3 = src[f16 + 3];
    uint4 p;
    p.x = sgnword(v0);
    p.y = sgnword(v1);
    p.z = sgnword(v2);
    p.w = sgnword(v3);
    dst[o16] = p;
}

// ---------------- GEMM + sign kernel (verified R12 structure) ----------------
__global__ void __launch_bounds__(256, 2) binlinear_gemm_kernel(float* __restrict__ out) {
    extern __shared__ int8_t smem[];
    const uint32_t sb = smem_u32(smem);
    const int tid = threadIdx.x;
    const int wid = tid >> 5;
    const int lane = tid & 31;
    const int g = lane >> 2;      // 0..7
    const int tig = lane & 3;     // 0..3
    const int mblk = blockIdx.y;
    const int nblk = blockIdx.x;
    const int m0 = mblk * TM;
    const int n0 = nblk * TN;
    const int wm = (wid & 3) * 32;     // warp M offset
    const int wn = (wid >> 2) * 64;    // warp N offset

    if (tid == 0) {
        #pragma unroll
        for (int s = 0; s < ST; ++s) {
            MBARRIER_INIT(sb + OFF_FULL + s * 8, 1);    // one expect_tx arrive + 32KB tx
            MBARRIER_INIT(sb + OFF_EMPTY + s * 8, 8);   // one arrive per warp
        }
    }
    __syncthreads();

    // per-lane ldmatrix bases in the swizzled 128B-row layout
    const int rowA0 = wm + (lane & 15);
    const uint32_t aRow0 = (uint32_t)rowA0 * 128;
    const uint32_t aRow1 = aRow0 + 16 * 128;
    const uint32_t swzA = (uint32_t)(rowA0 & 7) << 4;
    const uint32_t asegb = (uint32_t)(lane >> 4) << 4;       // 0 or 16

    const int rowB = wn + (lane >> 4) * 8 + (lane & 7);
    const uint32_t bRow = (uint32_t)rowB * 128;
    const uint32_t swzB = (uint32_t)(rowB & 7) << 4;
    const uint32_t bsegb = (uint32_t)(lane & 8) << 1;        // 0 or 16

    int c[2][8][4];
    #pragma unroll
    for (int mt = 0; mt < 2; ++mt)
        #pragma unroll
        for (int nt = 0; nt < 8; ++nt)
            #pragma unroll
            for (int r = 0; r < 4; ++r) c[mt][nt][r] = 0;

    const int8_t* gA = g_A2 + (size_t)(mblk * 16) * TILE_BYTES;  // + kc*16KB
    const int8_t* gB = g_B2 + (size_t)(nblk * 16) * TILE_BYTES;

    int pst = 0, pph = 1;
    int cst = 0, cph = 0;

    // prologue: tid0 arms stages 0..ST-2
    if (tid == 0) {
        #pragma unroll
        for (int s = 0; s < ST - 1; ++s) {
            const uint32_t full = sb + OFF_FULL + s * 8;
            MBARRIER_EXPECT_TX(full, STAGE);
            const uint32_t Ab = sb + SMEM_DATA + s * STAGE;
            CP_BULK_G2S(Ab, gA + (size_t)s * TILE_BYTES, TILE_BYTES, full);
            CP_BULK_G2S(Ab + A_ST, gB + (size_t)s * TILE_BYTES, TILE_BYTES, full);
        }
    }
    pst = ST - 1;  // next produce target (stage 2), phase still 1

    for (int i = 0; i < NK; ++i) {
        if (tid == 0 && i + ST - 1 < NK) {
            MBARRIER_WAIT_PARITY(sb + OFF_EMPTY + pst * 8, pph);
            const uint32_t full = sb + OFF_FULL + pst * 8;
            MBARRIER_EXPECT_TX(full, STAGE);
            const uint32_t Ab = sb + SMEM_DATA + pst * STAGE;
            const size_t kc = (size_t)(i + ST - 1) * TILE_BYTES;
            CP_BULK_G2S(Ab, gA + kc, TILE_BYTES, full);
            CP_BULK_G2S(Ab + A_ST, gB + kc, TILE_BYTES, full);
        }
        if (tid == 0) { if (++pst == ST) { pst = 0; pph ^= 1; } }

        // consume stage cst
        MBARRIER_WAIT_PARITY(sb + OFF_FULL + cst * 8, cph);
        const uint32_t Ab = sb + SMEM_DATA + cst * STAGE;
        const uint32_t Bb = Ab + A_ST;
        #pragma unroll
        for (int ks = 0; ks < 4; ++ks) {
            const uint32_t k0 = (uint32_t)ks * 32;
            uint32_t a[2][4];
            ldm_x4(a[0], Ab + aRow0 + ((asegb + k0) ^ swzA));
            ldm_x4(a[1], Ab + aRow1 + ((asegb + k0) ^ swzA));
            #pragma unroll
            for (int p = 0; p < 4; ++p) {
                uint32_t bt[4];
                ldm_x4(bt, Bb + bRow + (uint32_t)p * 2048 + ((bsegb + k0) ^ swzB));
                MMA_S8(c[0][2 * p + 0], a[0], bt[0], bt[1]);
                MMA_S8(c[0][2 * p + 1], a[0], bt[2], bt[3]);
                MMA_S8(c[1][2 * p + 0], a[1], bt[0], bt[1]);
                MMA_S8(c[1][2 * p + 1], a[1], bt[2], bt[3]);
            }
        }
        __syncwarp();
        if (lane == 0) MBARRIER_ARRIVE(sb + OFF_EMPTY + cst * 8);
        if (++cst == ST) { cst = 0; cph ^= 1; }
    }

    // ---- epilogue: sign -> float, 8B vectorized stores ----
    #pragma unroll
    for (int mt = 0; mt < 2; ++mt) {
        const int row0 = m0 + wm + mt * 16 + g;
        float* o0 = out + (size_t)row0 * DN + n0 + wn;
        float* o1 = out + (size_t)(row0 + 8) * DN + n0 + wn;
        #pragma unroll
        for (int nt = 0; nt < 8; ++nt) {
            const int col = nt * 8 + tig * 2;
            float2 v0 = make_float2(isgn(c[mt][nt][0]), isgn(c[mt][nt][1]));
            float2 v1 = make_float2(isgn(c[mt][nt][2]), isgn(c[mt][nt][3]));
            *reinterpret_cast<float2*>(o0 + col) = v0;
            *reinterpret_cast<float2*>(o1 + col) = v1;
        }
    }
}

// ---------------- launch ----------------
extern "C" void kernel_launch(void* const* d_in, const int* in_sizes, int n_in,
                              void* d_out, int out_size) {
    const float* a = (const float*)d_in[0];
    const float* w = (const float*)d_in[1];
    if (n_in >= 2 && in_sizes[0] < in_sizes[1]) {
        const float* t = a; a = w; w = t;
    }

    {
        int total = NA16 + NW16;   // 1.31M threads
        cvt_kernel<<<(total + 255) / 256, 256>>>((const uint4*)a, (const uint4*)w);
    }

    static bool attr_set = false;
    if (!attr_set) {
        cudaFuncSetAttribute(binlinear_gemm_kernel,
                             cudaFuncAttributeMaxDynamicSharedMemorySize, SMEM_BYTES);
        attr_set = true;
    }
    dim3 grid(DN / TN, DM / TM);   // (16, 64)
    binlinear_gemm_kernel<<<grid, 256, SMEM_BYTES>>>((float*)d_out);
}